// round 2
// baseline (speedup 1.0000x reference)
#include <cuda_runtime.h>

// FourierBlock: B=32, L=2048, H=8, E=64, MODES=64
// y = irfft( place_low64( einsum('bhim,hiom', gather(rfft(q^T), index), W) ), n=L )
//
// Implemented as 3 dense contractions (no FFT needed; only 64 modes live):
//  K1: X[b,h,i,(re|im)m] = q^T @ [cos|-sin](2*pi*idx[m]*l/L)       [16384x2048]@[2048x128]
//  K2: O[b,h,o,m] = sum_i X[b,h,i,m] * (Wr + i Wi)[h,i,o,m]        small
//  K3: y[b,h,o,l] = sum_m scaled [cos|-sin](2*pi*m*l/L) combo      [16384x128]@[128x2048]

#define NB 32
#define NL 2048
#define NH 8
#define NE 64
#define NM 64

// ---------------- scratch (device globals; no allocs allowed) ----------------
__device__ float g_FB[NL * 128];                 // forward basis [l][k]  k<64: cos, k>=64: -sin (freq=index[k%64])
__device__ float g_IB[128 * NL];                 // inverse basis [k][l]  with 1/L and factor-2 folded in
__device__ float g_WtR[NH * NM * NE * NE];       // [h][m][i][o]
__device__ float g_WtI[NH * NM * NE * NE];
__device__ float g_XF[2 * NB * NH * 128 * NE];   // [part][b][h][k][e]  (K split into 2 halves over l)
__device__ float g_O2[NB * NH * 128 * NE];       // [b][h][k][o]  k<64: re(m=k), k>=64: im(m=k-64)

// ---------------- K0a: basis tables ----------------
__global__ __launch_bounds__(256) void k_basis(const int* __restrict__ index) {
    int t = blockIdx.x * blockDim.x + threadIdx.x;     // 0..262143
    if (t >= NL * 128) return;
    int l = t >> 7;
    int k = t & 127;
    int kf = k & 63;

    // forward: freq = index[kf]
    int f = index[kf];
    int p = (f * l) & (NL - 1);                        // exact integer phase
    float s, c;
    sincospif((float)p * (1.0f / 1024.0f), &s, &c);    // angle = 2*pi*p/2048 = pi*p/1024
    g_FB[t] = (k < 64) ? c : -s;

    // inverse: freq = kf (modes placed in slots 0..63), ducc c2r convention:
    //   y_l = (1/L)[Re X0 + 2*sum_{f>=1}(Re X_f cos - Im X_f sin)]
    int p2 = (kf * l) & (NL - 1);
    sincospif((float)p2 * (1.0f / 1024.0f), &s, &c);
    float amp = (kf == 0) ? ((k < 64) ? (1.0f / (float)NL) : 0.0f)
                          : (2.0f / (float)NL);
    g_IB[k * NL + l] = (k < 64) ? amp * c : -amp * s;
}

// ---------------- K0b: transpose W[h][i][o][m] -> Wt[h][m][i][o] ----------------
__global__ __launch_bounds__(256) void k_wt(const float* __restrict__ wr,
                                            const float* __restrict__ wi) {
    __shared__ float sm[64][65];
    int h = blockIdx.x >> 6;
    int i = blockIdx.x & 63;
    int t = threadIdx.x;
    const float* src = wr + (size_t)((h * 64 + i) * 64) * 64;   // [o][m] slab, m contiguous
    float* dst = g_WtR;
#pragma unroll
    for (int pass = 0; pass < 2; pass++) {
#pragma unroll
        for (int r = 0; r < 16; r++) {
            int idx = r * 256 + t;
            sm[idx >> 6][idx & 63] = src[idx];                  // sm[o][m], coalesced read
        }
        __syncthreads();
#pragma unroll
        for (int r = 0; r < 16; r++) {
            int idx = r * 256 + t;
            int m = idx >> 6, o = idx & 63;
            dst[(size_t)((h * 64 + m) * 64 + i) * 64 + o] = sm[o][m];  // coalesced write in o
        }
        __syncthreads();
        src = wi + (size_t)((h * 64 + i) * 64) * 64;
        dst = g_WtI;
    }
}

// ---------------- K1: forward DFT  per (b,h,part): [64e x 1024l] @ [1024l x 128k] ----------------
__global__ __launch_bounds__(256) void k_fwd(const float* __restrict__ q) {
    __shared__ __align__(16) float As[32][64];    // [l][e]
    __shared__ __align__(16) float Bs[32][128];   // [l][k]
    int bh = blockIdx.x;                          // b*8+h
    int b = bh >> 3, h = bh & 7;
    int p = blockIdx.y;                           // K-split half
    int t = threadIdx.x;
    int tx = t & 15, ty = t >> 4;

    float acc[4][8];
#pragma unroll
    for (int e = 0; e < 4; e++)
#pragma unroll
        for (int j = 0; j < 8; j++) acc[e][j] = 0.0f;

    // q[b,l,h,e] = q[ b*L*H*E + l*H*E + h*E + e ]
    const float* qb = q + (size_t)b * (NL * NH * NE) + h * NE + (size_t)p * 1024 * (NH * NE);
    const float* fb = g_FB + (size_t)p * 1024 * 128;

    for (int lt = 0; lt < 32; lt++) {
#pragma unroll
        for (int r = 0; r < 2; r++) {             // 32x64 A tile
            int f2 = r * 256 + t;
            int l = f2 >> 4, e4 = (f2 & 15) * 4;
            *(float4*)&As[l][e4] = *(const float4*)&qb[(size_t)(lt * 32 + l) * (NH * NE) + e4];
        }
#pragma unroll
        for (int r = 0; r < 4; r++) {             // 32x128 B tile
            int f2 = r * 256 + t;
            int l = f2 >> 5, k4 = (f2 & 31) * 4;
            *(float4*)&Bs[l][k4] = *(const float4*)&fb[(size_t)(lt * 32 + l) * 128 + k4];
        }
        __syncthreads();
#pragma unroll
        for (int l = 0; l < 32; l++) {
            float4 a  = *(float4*)&As[l][ty * 4];
            float4 b0 = *(float4*)&Bs[l][tx * 4];        // k = tx*4 + j       (j<4)
            float4 b1 = *(float4*)&Bs[l][64 + tx * 4];   // k = 64 + tx*4 + j  (j>=4)
            float av[4] = {a.x, a.y, a.z, a.w};
            float bv[8] = {b0.x, b0.y, b0.z, b0.w, b1.x, b1.y, b1.z, b1.w};
#pragma unroll
            for (int e = 0; e < 4; e++)
#pragma unroll
                for (int j = 0; j < 8; j++) acc[e][j] += av[e] * bv[j];
        }
        __syncthreads();
    }

    float* xf = g_XF + (size_t)(p * (NB * NH) + bh) * 128 * NE;
#pragma unroll
    for (int j = 0; j < 8; j++) {
        int k = (j < 4) ? (tx * 4 + j) : (64 + tx * 4 + (j - 4));
        *(float4*)&xf[k * NE + ty * 4] = make_float4(acc[0][j], acc[1][j], acc[2][j], acc[3][j]);
    }
}

// ---------------- K2: mode mixing  per (h,m): [32b x 64i] @ complex [64i x 64o] ----------------
__global__ __launch_bounds__(256) void k_mix() {
    __shared__ float Xr[32][64];
    __shared__ float Xi[32][64];
    __shared__ float Wr[64][64];
    __shared__ float Wi[64][64];
    int h = blockIdx.x >> 6;
    int m = blockIdx.x & 63;
    int t = threadIdx.x;

#pragma unroll
    for (int r = 0; r < 8; r++) {
        int idx = r * 256 + t;
        int b = idx >> 6, i = idx & 63;
        size_t base0 = ((size_t)(b * 8 + h) * 128);
        size_t base1 = ((size_t)(NB * NH + b * 8 + h) * 128);
        Xr[b][i] = g_XF[(base0 + m) * NE + i] + g_XF[(base1 + m) * NE + i];
        Xi[b][i] = g_XF[(base0 + 64 + m) * NE + i] + g_XF[(base1 + 64 + m) * NE + i];
    }
#pragma unroll
    for (int r = 0; r < 16; r++) {
        int idx = r * 256 + t;
        int i = idx >> 6, o = idx & 63;
        size_t wbase = (size_t)((h * 64 + m) * 64 + i) * 64 + o;
        Wr[i][o] = g_WtR[wbase];
        Wi[i][o] = g_WtI[wbase];
    }
    __syncthreads();

    int b = t >> 3;
    int og = (t & 7) * 8;
    float ar[8], ai[8];
#pragma unroll
    for (int j = 0; j < 8; j++) { ar[j] = 0.0f; ai[j] = 0.0f; }

    for (int i = 0; i < 64; i++) {
        float xr = Xr[b][i], xi = Xi[b][i];
#pragma unroll
        for (int j = 0; j < 8; j++) {
            float wr = Wr[i][og + j], wi = Wi[i][og + j];
            ar[j] += xr * wr - xi * wi;
            ai[j] += xr * wi + xi * wr;
        }
    }

    float* o2r = g_O2 + ((size_t)(b * 8 + h) * 128 + m) * NE + og;   // k=m (re)
    float* o2i = o2r + 64 * NE;                                      // k=64+m (im)
    *(float4*)&o2r[0] = make_float4(ar[0], ar[1], ar[2], ar[3]);
    *(float4*)&o2r[4] = make_float4(ar[4], ar[5], ar[6], ar[7]);
    *(float4*)&o2i[0] = make_float4(ai[0], ai[1], ai[2], ai[3]);
    *(float4*)&o2i[4] = make_float4(ai[4], ai[5], ai[6], ai[7]);
}

// ---------------- K3: inverse  per (b,h,ltile): [64o x 128k] @ [128k x 128l] ----------------
__global__ __launch_bounds__(256) void k_inv(float* __restrict__ out) {
    __shared__ __align__(16) float As[32][64];    // [k][o]
    __shared__ __align__(16) float Bs[32][128];   // [k][l]
    int bh = blockIdx.x;
    int l0 = blockIdx.y * 128;
    int t = threadIdx.x;
    int tx = t & 15, ty = t >> 4;

    float acc[4][8];
#pragma unroll
    for (int e = 0; e < 4; e++)
#pragma unroll
        for (int j = 0; j < 8; j++) acc[e][j] = 0.0f;

    const float* a_src = g_O2 + (size_t)bh * 128 * NE;

    for (int kt = 0; kt < 4; kt++) {
#pragma unroll
        for (int r = 0; r < 2; r++) {             // 32x64 A tile
            int f2 = r * 256 + t;
            int kk = f2 >> 4, o4 = (f2 & 15) * 4;
            *(float4*)&As[kk][o4] = *(const float4*)&a_src[(size_t)(kt * 32 + kk) * NE + o4];
        }
#pragma unroll
        for (int r = 0; r < 4; r++) {             // 32x128 B tile
            int f2 = r * 256 + t;
            int kk = f2 >> 5, l4 = (f2 & 31) * 4;
            *(float4*)&Bs[kk][l4] = *(const float4*)&g_IB[(size_t)(kt * 32 + kk) * NL + l0 + l4];
        }
        __syncthreads();
#pragma unroll
        for (int kk = 0; kk < 32; kk++) {
            float4 a  = *(float4*)&As[kk][ty * 4];
            float4 b0 = *(float4*)&Bs[kk][tx * 4];
            float4 b1 = *(float4*)&Bs[kk][64 + tx * 4];
            float av[4] = {a.x, a.y, a.z, a.w};
            float bv[8] = {b0.x, b0.y, b0.z, b0.w, b1.x, b1.y, b1.z, b1.w};
#pragma unroll
            for (int e = 0; e < 4; e++)
#pragma unroll
                for (int j = 0; j < 8; j++) acc[e][j] += av[e] * bv[j];
        }
        __syncthreads();
    }

    float* yo = out + (size_t)bh * 64 * NL + l0;
#pragma unroll
    for (int e = 0; e < 4; e++) {
        int o = ty * 4 + e;
        *(float4*)&yo[(size_t)o * NL + tx * 4]      = make_float4(acc[e][0], acc[e][1], acc[e][2], acc[e][3]);
        *(float4*)&yo[(size_t)o * NL + 64 + tx * 4] = make_float4(acc[e][4], acc[e][5], acc[e][6], acc[e][7]);
    }
}

// ---------------- launch ----------------
extern "C" void kernel_launch(void* const* d_in, const int* in_sizes, int n_in,
                              void* d_out, int out_size) {
    const float* q     = (const float*)d_in[0];
    // d_in[1] = k, d_in[2] = v : unused by FourierBlock
    const float* wreal = (const float*)d_in[3];
    const float* wimag = (const float*)d_in[4];
    const int*   index = (const int*)d_in[5];
    float* out = (float*)d_out;

    k_basis<<<(NL * 128 + 255) / 256, 256>>>(index);
    k_wt<<<NH * NE, 256>>>(wreal, wimag);
    k_fwd<<<dim3(NB * NH, 2), 256>>>(q);
    k_mix<<<NH * NM, 256>>>();
    k_inv<<<dim3(NB * NH, 16), 256>>>(out);
}